// round 2
// baseline (speedup 1.0000x reference)
#include <cuda_runtime.h>
#include <math.h>

// Problem: B=4, T=4096, D=1024, H=16, hd=64; M = B*T = 16384
#define Tn 4096

// Scratch (no allocations allowed -> __device__ globals)
__device__ float g_qkv[50331648];   // [16384, 3072]  q|k|v (3 x [H][64])
__device__ float g_attn[16777216];  // [16384, 1024]  attention out (pre w_out)
__device__ float g_kv[262144];      // [B*H, 64, 64]  sum_t k_feat (x) v
__device__ float g_ksum[4096];      // [B*H, 64]      sum_t k_feat

// ---------------------------------------------------------------------------
__global__ void __launch_bounds__(256) zero_kernel() {
  int i = blockIdx.x * 256 + threadIdx.x;   // grid covers exactly 262144
  g_kv[i] = 0.0f;
  if (i < 4096) g_ksum[i] = 0.0f;
}

// ---------------------------------------------------------------------------
// fp32 SGEMM, C[m,n] = sum_k A[m,k]*B[n,k] ("NT", both K-major).
// 128x128 tile, K-slice 16, 8x8 micro-tile, 256 threads.
// Register-prefetch software pipeline: next tile's GMEM loads issued before
// compute on the current smem tile, stored to smem after the barrier.
template <int N>
__device__ __forceinline__ void sgemm_nt_body(const float* __restrict__ A,
                                              const float* __restrict__ Bm,
                                              float* __restrict__ C) {
  const int K = 1024;
  __shared__ float As[16][132];
  __shared__ float Bs[16][132];
  int tid = threadIdx.x;
  int tx = tid & 15, ty = tid >> 4;
  const float* Ab = A + (size_t)blockIdx.y * 128 * K;
  const float* Bb = Bm + (size_t)blockIdx.x * 128 * K;

  // Each thread loads 2 (row, c4) pairs for A and B per K-slice.
  int r0 = tid >> 2;                 // rows 0..63   (l=0)
  int r1 = (tid + 256) >> 2;         // rows 64..127 (l=1)
  int c4 = (tid & 3) << 2;

  float acc[8][8];
#pragma unroll
  for (int i = 0; i < 8; i++)
#pragma unroll
    for (int j = 0; j < 8; j++) acc[i][j] = 0.0f;

  float4 pa0, pa1, pb0, pb1;
  // Prologue: fetch tile kk=0
  pa0 = *(const float4*)(Ab + (size_t)r0 * K + c4);
  pa1 = *(const float4*)(Ab + (size_t)r1 * K + c4);
  pb0 = *(const float4*)(Bb + (size_t)r0 * K + c4);
  pb1 = *(const float4*)(Bb + (size_t)r1 * K + c4);

  for (int kk = 0; kk < K; kk += 16) {
    // Commit prefetched tile to smem
    As[c4 + 0][r0] = pa0.x; As[c4 + 1][r0] = pa0.y;
    As[c4 + 2][r0] = pa0.z; As[c4 + 3][r0] = pa0.w;
    As[c4 + 0][r1] = pa1.x; As[c4 + 1][r1] = pa1.y;
    As[c4 + 2][r1] = pa1.z; As[c4 + 3][r1] = pa1.w;
    Bs[c4 + 0][r0] = pb0.x; Bs[c4 + 1][r0] = pb0.y;
    Bs[c4 + 2][r0] = pb0.z; Bs[c4 + 3][r0] = pb0.w;
    Bs[c4 + 0][r1] = pb1.x; Bs[c4 + 1][r1] = pb1.y;
    Bs[c4 + 2][r1] = pb1.z; Bs[c4 + 3][r1] = pb1.w;
    __syncthreads();

    // Prefetch next tile into registers (overlaps with compute below)
    if (kk + 16 < K) {
      pa0 = *(const float4*)(Ab + (size_t)r0 * K + kk + 16 + c4);
      pa1 = *(const float4*)(Ab + (size_t)r1 * K + kk + 16 + c4);
      pb0 = *(const float4*)(Bb + (size_t)r0 * K + kk + 16 + c4);
      pb1 = *(const float4*)(Bb + (size_t)r1 * K + kk + 16 + c4);
    }

#pragma unroll
    for (int k = 0; k < 16; k++) {
      float4 a0 = *(const float4*)&As[k][ty << 3];
      float4 a1 = *(const float4*)&As[k][(ty << 3) + 4];
      float4 b0 = *(const float4*)&Bs[k][tx << 3];
      float4 b1 = *(const float4*)&Bs[k][(tx << 3) + 4];
      float a[8] = {a0.x, a0.y, a0.z, a0.w, a1.x, a1.y, a1.z, a1.w};
      float b[8] = {b0.x, b0.y, b0.z, b0.w, b1.x, b1.y, b1.z, b1.w};
#pragma unroll
      for (int i = 0; i < 8; i++)
#pragma unroll
        for (int j = 0; j < 8; j++)
          acc[i][j] = fmaf(a[i], b[j], acc[i][j]);
    }
    __syncthreads();
  }

  size_t crow = (size_t)blockIdx.y * 128 + (ty << 3);
  int ccol = (blockIdx.x << 7) + (tx << 3);
#pragma unroll
  for (int i = 0; i < 8; i++) {
    *(float4*)(C + (crow + i) * N + ccol) =
        make_float4(acc[i][0], acc[i][1], acc[i][2], acc[i][3]);
    *(float4*)(C + (crow + i) * N + ccol + 4) =
        make_float4(acc[i][4], acc[i][5], acc[i][6], acc[i][7]);
  }
}

__global__ void __launch_bounds__(256) qkv_gemm(const float* __restrict__ x,
                                                const float* __restrict__ w) {
  sgemm_nt_body<3072>(x, w, g_qkv);
}
__global__ void __launch_bounds__(256) out_gemm(const float* __restrict__ w,
                                                float* __restrict__ out) {
  sgemm_nt_body<1024>(g_attn, w, out);
}

// ---------------------------------------------------------------------------
// RoPE angle, matching the reference's fp32 rounding exactly:
//   theta_ref = fp32( fp32(t) * fp32(inv_freq) )
// then range-reduce THAT value in double and take sinf/cosf of the reduced
// argument (accurate regardless of --use_fast_math).
#define LN1E4_OVER_32 0.28782308398950104   // ln(10000)/32
#define TWO_PI_D 6.283185307179586
#define INV2PI_D 0.15915494309189535

__device__ __forceinline__ float2 rope_sc(int t, float ivf_f) {
  float th_f = __fmul_rn((float)t, ivf_f);       // reference's rounded angle
  double th = (double)th_f;
  float rf = (float)(th - floor(th * INV2PI_D) * TWO_PI_D);
  return make_float2(sinf(rf), cosf(rf));
}

// ---------------------------------------------------------------------------
// kv[b,h,d,v] = sum_t kfeat[t,d]*v[t,v];  ksum[b,h,d] = sum_t kfeat[t,d]
// kfeat = elu(rope(k)) + 1.  One block per (b*h, 256-token chunk), atomics
// merge partials into zeroed scratch.
__global__ void __launch_bounds__(256) kv_accum_kernel() {
  int bh = blockIdx.x;            // 0..63
  int b = bh >> 4, h = bh & 15;
  int t0 = blockIdx.y << 8;
  int tid = threadIdx.x;
  int d = tid >> 2;               // thread owns kv[d][v0..v0+15]
  int v0 = (tid & 3) << 4;
  bool lead = (tid & 3) == 0;
  int p = tid & 31;               // loader role: RoPE pair index
  int ltt = tid >> 5;             // loader role: token within 8-token stage

  __shared__ float kf[8][64];
  __shared__ float vv[8][64];

  float acc[16];
#pragma unroll
  for (int i = 0; i < 16; i++) acc[i] = 0.0f;
  float ks = 0.0f;

  float ivf_f = (float)exp(-(double)p * LN1E4_OVER_32);

  for (int ts = 0; ts < 256; ts += 8) {
    int t = t0 + ts + ltt;
    float2 sc = rope_sc(t, ivf_f);
    float s = sc.x, c = sc.y;

    size_t base = ((size_t)(b * Tn + t)) * 3072 + (h << 6);
    float xe = g_qkv[base + 1024 + p];       // k even half
    float xo = g_qkv[base + 1056 + p];       // k odd half
    float ke = fmaf(xe, c, -xo * s);
    float ko = fmaf(xe, s, xo * c);
    kf[ltt][p]      = ke > 0.0f ? ke + 1.0f : expf(ke);
    kf[ltt][p + 32] = ko > 0.0f ? ko + 1.0f : expf(ko);
    vv[ltt][p]      = g_qkv[base + 2048 + p];
    vv[ltt][p + 32] = g_qkv[base + 2080 + p];
    __syncthreads();

#pragma unroll
    for (int tt = 0; tt < 8; tt++) {
      float kd = kf[tt][d];
      const float4* vr = (const float4*)&vv[tt][v0];
      float4 w0 = vr[0], w1 = vr[1], w2 = vr[2], w3 = vr[3];
      acc[0]  = fmaf(kd, w0.x, acc[0]);
      acc[1]  = fmaf(kd, w0.y, acc[1]);
      acc[2]  = fmaf(kd, w0.z, acc[2]);
      acc[3]  = fmaf(kd, w0.w, acc[3]);
      acc[4]  = fmaf(kd, w1.x, acc[4]);
      acc[5]  = fmaf(kd, w1.y, acc[5]);
      acc[6]  = fmaf(kd, w1.z, acc[6]);
      acc[7]  = fmaf(kd, w1.w, acc[7]);
      acc[8]  = fmaf(kd, w2.x, acc[8]);
      acc[9]  = fmaf(kd, w2.y, acc[9]);
      acc[10] = fmaf(kd, w2.z, acc[10]);
      acc[11] = fmaf(kd, w2.w, acc[11]);
      acc[12] = fmaf(kd, w3.x, acc[12]);
      acc[13] = fmaf(kd, w3.y, acc[13]);
      acc[14] = fmaf(kd, w3.z, acc[14]);
      acc[15] = fmaf(kd, w3.w, acc[15]);
      if (lead) ks += kd;
    }
    __syncthreads();
  }

  float* kvg = g_kv + (bh << 12) + (d << 6) + v0;
#pragma unroll
  for (int i = 0; i < 16; i++) atomicAdd(kvg + i, acc[i]);
  if (lead) atomicAdd(&g_ksum[(bh << 6) + d], ks);
}

// ---------------------------------------------------------------------------
// out[b,t,h,:] = (qfeat . kv[b,h]) / max(qfeat . ksum[b,h], 1e-6)
// qfeat = elu(rope(q)*hd^-0.5) + 1.  One thread per token; kv tile in smem.
__global__ void __launch_bounds__(128) attn_out_kernel() {
  int bh = blockIdx.x;
  int b = bh >> 4, h = bh & 15;
  int t = (blockIdx.y << 7) + threadIdx.x;

  __shared__ float kvs[4096];
  __shared__ float kss[64];
  __shared__ float ivfs[32];

  const float4* src = (const float4*)(g_kv + (bh << 12));
  for (int i = threadIdx.x; i < 1024; i += 128)
    ((float4*)kvs)[i] = src[i];
  if (threadIdx.x < 64) kss[threadIdx.x] = g_ksum[(bh << 6) + threadIdx.x];
  if (threadIdx.x < 32)
    ivfs[threadIdx.x] = (float)exp(-(double)threadIdx.x * LN1E4_OVER_32);
  __syncthreads();

  size_t base = ((size_t)(b * Tn + t)) * 3072 + (h << 6);

  float qf[64];
#pragma unroll
  for (int pc = 0; pc < 8; pc++) {            // 4 pairs per chunk
    float4 xe4 = *(const float4*)(g_qkv + base + (pc << 2));
    float4 xo4 = *(const float4*)(g_qkv + base + 32 + (pc << 2));
    float xes[4] = {xe4.x, xe4.y, xe4.z, xe4.w};
    float xos[4] = {xo4.x, xo4.y, xo4.z, xo4.w};
#pragma unroll
    for (int j = 0; j < 4; j++) {
      int pp = (pc << 2) + j;
      float2 sc = rope_sc(t, ivfs[pp]);
      float s = sc.x, c = sc.y;
      float qe = fmaf(xes[j], c, -xos[j] * s) * 0.125f;  // hd^-0.5
      float qo = fmaf(xes[j], s, xos[j] * c) * 0.125f;
      qf[pp]      = qe > 0.0f ? qe + 1.0f : expf(qe);
      qf[pp + 32] = qo > 0.0f ? qo + 1.0f : expf(qo);
    }
  }

  float den = 0.0f;
#pragma unroll
  for (int dd = 0; dd < 64; dd++) den = fmaf(qf[dd], kss[dd], den);
  den = fmaxf(den, 1e-6f);
  float inv = 1.0f / den;

  float4 o[16];
#pragma unroll
  for (int i = 0; i < 16; i++) o[i] = make_float4(0.f, 0.f, 0.f, 0.f);
#pragma unroll
  for (int dd = 0; dd < 64; dd++) {
    float qd = qf[dd];
    const float4* row = (const float4*)&kvs[dd << 6];
#pragma unroll
    for (int i = 0; i < 16; i++) {
      float4 rv = row[i];
      o[i].x = fmaf(qd, rv.x, o[i].x);
      o[i].y = fmaf(qd, rv.y, o[i].y);
      o[i].z = fmaf(qd, rv.z, o[i].z);
      o[i].w = fmaf(qd, rv.w, o[i].w);
    }
  }

  float* op = g_attn + (((size_t)(b * Tn + t)) << 10) + (h << 6);
#pragma unroll
  for (int i = 0; i < 16; i++)
    *(float4*)(op + (i << 2)) =
        make_float4(o[i].x * inv, o[i].y * inv, o[i].z * inv, o[i].w * inv);
}

// ---------------------------------------------------------------------------
extern "C" void kernel_launch(void* const* d_in, const int* in_sizes, int n_in,
                              void* d_out, int out_size) {
  (void)in_sizes; (void)n_in; (void)out_size;
  const float* x     = (const float*)d_in[0];
  const float* w_qkv = (const float*)d_in[1];
  const float* w_out = (const float*)d_in[2];
  float* out = (float*)d_out;

  zero_kernel<<<1024, 256>>>();
  qkv_gemm<<<dim3(3072 / 128, 16384 / 128), 256>>>(x, w_qkv);   // (24, 128)
  kv_accum_kernel<<<dim3(64, 16), 256>>>();
  attn_out_kernel<<<dim3(64, 32), 128>>>();
  out_gemm<<<dim3(1024 / 128, 16384 / 128), 256>>>(w_out, out); // (8, 128)
}

// round 7
// speedup vs baseline: 2.4871x; 2.4871x over previous
#include <cuda_runtime.h>
#include <cuda_bf16.h>
#include <math.h>
#include <stdint.h>

// Problem: B=4, T=4096, D=1024, H=16, hd=64; M = B*T = 16384
#define Tn 4096

// ---------------------------------------------------------------------------
// Scratch (__device__ globals; no allocations allowed)
__device__ float          g_qkv[50331648];     // [16384,3072] fp32 q|k|v
__device__ __nv_bfloat16  g_x_hi[16777216],   g_x_lo[16777216];    // [16384,1024]
__device__ __nv_bfloat16  g_wqkv_hi[3145728], g_wqkv_lo[3145728];  // [3072,1024]
__device__ __nv_bfloat16  g_wout_hi[1048576], g_wout_lo[1048576];  // [1024,1024]
__device__ __nv_bfloat16  g_attn_hi[16777216],g_attn_lo[16777216]; // [16384,1024]
__device__ float          g_kv[262144];        // [B*H,64,64]
__device__ float          g_ksum[4096];        // [B*H,64]

// ---------------------------------------------------------------------------
// Baseline-PTX helpers (all legal on compute_100: sm_75/80-era instructions)
__device__ __forceinline__ uint32_t smem_u32(const void* p) {
  uint32_t a;
  asm("{ .reg .u64 t; cvta.to.shared.u64 t, %1; cvt.u32.u64 %0, t; }"
      : "=r"(a) : "l"(p));
  return a;
}
__device__ __forceinline__ void cp16(uint32_t dst, const void* src) {
  asm volatile("cp.async.cg.shared.global [%0], [%1], 16;"
               :: "r"(dst), "l"(src) : "memory");
}
__device__ __forceinline__ void cp_commit() {
  asm volatile("cp.async.commit_group;" ::: "memory");
}
template <int n>
__device__ __forceinline__ void cp_wait() {
  asm volatile("cp.async.wait_group %0;" :: "n"(n) : "memory");
}
__device__ __forceinline__ void ldm4(uint32_t& r0, uint32_t& r1, uint32_t& r2,
                                     uint32_t& r3, uint32_t a) {
  asm volatile("ldmatrix.sync.aligned.m8n8.x4.shared.b16 {%0,%1,%2,%3}, [%4];"
               : "=r"(r0), "=r"(r1), "=r"(r2), "=r"(r3) : "r"(a));
}
__device__ __forceinline__ void mma16816(float* c, const uint32_t* a,
                                         const uint32_t* b) {
  asm volatile(
      "mma.sync.aligned.m16n8k16.row.col.f32.bf16.bf16.f32 "
      "{%0,%1,%2,%3}, {%4,%5,%6,%7}, {%8,%9}, {%0,%1,%2,%3};"
      : "+f"(c[0]), "+f"(c[1]), "+f"(c[2]), "+f"(c[3])
      : "r"(a[0]), "r"(a[1]), "r"(a[2]), "r"(a[3]), "r"(b[0]), "r"(b[1]));
}
__device__ __forceinline__ uint32_t swz(uint32_t off) {  // SW128
  return off ^ ((off >> 3) & 0x70);
}

// ---------------------------------------------------------------------------
// fp32 -> bf16 hi/lo split
__device__ __forceinline__ void split2(float v, unsigned short& h,
                                       unsigned short& l) {
  __nv_bfloat16 hb = __float2bfloat16_rn(v);
  h = __bfloat16_as_ushort(hb);
  l = __bfloat16_as_ushort(__float2bfloat16_rn(v - __bfloat162float(hb)));
}

__global__ void __launch_bounds__(256) conv_x(const float* __restrict__ in) {
  int i = blockIdx.x * 256 + threadIdx.x;   // n4 = 4194304
  float4 v = ((const float4*)in)[i];
  ushort4 h, l;
  split2(v.x, h.x, l.x); split2(v.y, h.y, l.y);
  split2(v.z, h.z, l.z); split2(v.w, h.w, l.w);
  ((ushort4*)g_x_hi)[i] = h;
  ((ushort4*)g_x_lo)[i] = l;
}
__global__ void __launch_bounds__(256) conv_wqkv(const float* __restrict__ in) {
  int i = blockIdx.x * 256 + threadIdx.x;   // n4 = 786432
  float4 v = ((const float4*)in)[i];
  ushort4 h, l;
  split2(v.x, h.x, l.x); split2(v.y, h.y, l.y);
  split2(v.z, h.z, l.z); split2(v.w, h.w, l.w);
  ((ushort4*)g_wqkv_hi)[i] = h;
  ((ushort4*)g_wqkv_lo)[i] = l;
}
// Also zeroes g_kv / g_ksum (grid 1024*256 == 262144 == len(g_kv)).
__global__ void __launch_bounds__(256) conv_wout(const float* __restrict__ in) {
  int i = blockIdx.x * 256 + threadIdx.x;   // n4 = 262144
  float4 v = ((const float4*)in)[i];
  ushort4 h, l;
  split2(v.x, h.x, l.x); split2(v.y, h.y, l.y);
  split2(v.z, h.z, l.z); split2(v.w, h.w, l.w);
  ((ushort4*)g_wout_hi)[i] = h;
  ((ushort4*)g_wout_lo)[i] = l;
  g_kv[i] = 0.0f;
  if (i < 4096) g_ksum[i] = 0.0f;
}

// ---------------------------------------------------------------------------
// bf16x3 GEMM via mma.sync (HMMA): C[m,n] = sum_k A[m,k]*B[n,k].
// CTA 128x128, Kc=64 (SW128 rows), 2-stage cp.async pipeline, 8 warps of
// 64x32 (4x4 m16n8k16 tiles), D += Ah*Bh + Ah*Bl + Al*Bh per k16.
// Stage layout (64KB): [A_hi 16K | A_lo 16K | B_hi 16K | B_lo 16K]; 2 stages.
template <int N>
__global__ void __launch_bounds__(256) gemm_mma(float* __restrict__ Cout) {
  extern __shared__ __align__(128) unsigned char smbuf[];
  const __nv_bfloat16* __restrict__ Ah_g = (N == 3072) ? g_x_hi : g_attn_hi;
  const __nv_bfloat16* __restrict__ Al_g = (N == 3072) ? g_x_lo : g_attn_lo;
  const __nv_bfloat16* __restrict__ Bh_g = (N == 3072) ? g_wqkv_hi : g_wout_hi;
  const __nv_bfloat16* __restrict__ Bl_g = (N == 3072) ? g_wqkv_lo : g_wout_lo;
  float* __restrict__ C = (N == 3072) ? g_qkv : Cout;

  int tid = threadIdx.x, lane = tid & 31, wid = tid >> 5;
  int m0 = blockIdx.y << 7, n0 = blockIdx.x << 7;
  int wm = (wid >> 2) << 6;   // warp m-offset: 0 / 64
  int wn = (wid & 3) << 5;    // warp n-offset: 0/32/64/96

  uint32_t sb = smem_u32(smbuf);

  auto stage_load = [&](int buf, int kk) {
    uint32_t d = sb + ((uint32_t)buf << 16);
#pragma unroll
    for (int it = 0; it < 4; it++) {
      int c = (it << 8) + tid;
      int r = c >> 3, sg = c & 7;                 // row 0..127, 16B-seg 0..7
      uint32_t off = swz((uint32_t)((r << 7) + (sg << 4)));
      size_t ga = (size_t)(m0 + r) * 1024 + kk + (sg << 3);
      size_t gb = (size_t)(n0 + r) * 1024 + kk + (sg << 3);
      cp16(d + off,         Ah_g + ga);
      cp16(d + 16384 + off, Al_g + ga);
      cp16(d + 32768 + off, Bh_g + gb);
      cp16(d + 49152 + off, Bl_g + gb);
    }
  };

  float acc[4][4][4];
#pragma unroll
  for (int i = 0; i < 4; i++)
#pragma unroll
    for (int j = 0; j < 4; j++)
#pragma unroll
      for (int q = 0; q < 4; q++) acc[i][j][q] = 0.0f;

  stage_load(0, 0);
  cp_commit();

  for (int ch = 0; ch < 16; ch++) {
    if (ch + 1 < 16) {
      stage_load((ch + 1) & 1, (ch + 1) << 6);
      cp_commit();
      cp_wait<1>();
    } else {
      cp_wait<0>();
    }
    __syncthreads();
    uint32_t bs = sb + ((uint32_t)(ch & 1) << 16);

#pragma unroll
    for (int k16 = 0; k16 < 4; k16++) {
      uint32_t Ah[4][4], Al[4][4], Bh[4][2], Bl[4][2];
      // A fragments: lanes 0-15 rows m0-15 (seg k+0), lanes 16-31 seg k+16B
      int ar = wm + (lane & 15);
      uint32_t ac = (uint32_t)((k16 << 5) + ((lane >> 4) << 4));
#pragma unroll
      for (int mt = 0; mt < 4; mt++) {
        uint32_t off = swz((uint32_t)(((ar + (mt << 4)) << 7)) + ac);
        ldm4(Ah[mt][0], Ah[mt][1], Ah[mt][2], Ah[mt][3], bs + off);
        ldm4(Al[mt][0], Al[mt][1], Al[mt][2], Al[mt][3], bs + 16384 + off);
      }
      // B fragments: lanes 0-7 rows n0-7 seg0, 8-15 rows n0-7 seg16,
      //              16-23 rows n8-15 seg0, 24-31 rows n8-15 seg16
      int br = wn + ((lane >> 4) << 3) + (lane & 7);
      uint32_t bc = (uint32_t)((k16 << 5) + (((lane >> 3) & 1) << 4));
#pragma unroll
      for (int np = 0; np < 2; np++) {
        uint32_t off = swz((uint32_t)(((br + (np << 4)) << 7)) + bc);
        uint32_t r0, r1, r2, r3;
        ldm4(r0, r1, r2, r3, bs + 32768 + off);
        Bh[np * 2][0] = r0; Bh[np * 2][1] = r1;
        Bh[np * 2 + 1][0] = r2; Bh[np * 2 + 1][1] = r3;
        ldm4(r0, r1, r2, r3, bs + 49152 + off);
        Bl[np * 2][0] = r0; Bl[np * 2][1] = r1;
        Bl[np * 2 + 1][0] = r2; Bl[np * 2 + 1][1] = r3;
      }
#pragma unroll
      for (int mt = 0; mt < 4; mt++)
#pragma unroll
        for (int nt = 0; nt < 4; nt++) {
          mma16816(acc[mt][nt], Ah[mt], Bh[nt]);
          mma16816(acc[mt][nt], Ah[mt], Bl[nt]);
          mma16816(acc[mt][nt], Al[mt], Bh[nt]);
        }
    }
    __syncthreads();
  }

  // Epilogue: c0,c1 at (row g, col 2*tg), c2,c3 at row g+8
  int g = lane >> 2, tg = lane & 3;
#pragma unroll
  for (int mt = 0; mt < 4; mt++) {
    int row = m0 + wm + (mt << 4) + g;
#pragma unroll
    for (int nt = 0; nt < 4; nt++) {
      int col = n0 + wn + (nt << 3) + (tg << 1);
      float* p0 = C + (size_t)row * N + col;
      float* p1 = C + (size_t)(row + 8) * N + col;
      p0[0] = acc[mt][nt][0]; p0[1] = acc[mt][nt][1];
      p1[0] = acc[mt][nt][2]; p1[1] = acc[mt][nt][3];
    }
  }
}

// ---------------------------------------------------------------------------
// RoPE angle, matching reference fp32 rounding: theta = fp32(t * inv_freq),
// then double range reduction + sinf/cosf of the reduced argument.
#define LN1E4_OVER_32 0.28782308398950104
#define TWO_PI_D 6.283185307179586
#define INV2PI_D 0.15915494309189535

__device__ __forceinline__ float2 rope_sc(int t, float ivf_f) {
  float th_f = __fmul_rn((float)t, ivf_f);
  double th = (double)th_f;
  float rf = (float)(th - floor(th * INV2PI_D) * TWO_PI_D);
  return make_float2(sinf(rf), cosf(rf));
}

// ---------------------------------------------------------------------------
__global__ void __launch_bounds__(256) kv_accum_kernel() {
  int bh = blockIdx.x;
  int b = bh >> 4, h = bh & 15;
  int t0 = blockIdx.y << 8;
  int tid = threadIdx.x;
  int d = tid >> 2;
  int v0 = (tid & 3) << 4;
  bool lead = (tid & 3) == 0;
  int p = tid & 31;
  int ltt = tid >> 5;

  __shared__ float kf[8][64];
  __shared__ float vv[8][64];

  float acc[16];
#pragma unroll
  for (int i = 0; i < 16; i++) acc[i] = 0.0f;
  float ks = 0.0f;

  float ivf_f = (float)exp(-(double)p * LN1E4_OVER_32);

  for (int ts = 0; ts < 256; ts += 8) {
    int t = t0 + ts + ltt;
    float2 sc = rope_sc(t, ivf_f);
    float s = sc.x, c = sc.y;

    size_t base = ((size_t)(b * Tn + t)) * 3072 + (h << 6);
    float xe = g_qkv[base + 1024 + p];
    float xo = g_qkv[base + 1056 + p];
    float ke = fmaf(xe, c, -xo * s);
    float ko = fmaf(xe, s, xo * c);
    kf[ltt][p]      = ke > 0.0f ? ke + 1.0f : expf(ke);
    kf[ltt][p + 32] = ko > 0.0f ? ko + 1.0f : expf(ko);
    vv[ltt][p]      = g_qkv[base + 2048 + p];
    vv[ltt][p + 32] = g_qkv[base + 2080 + p];
    __syncthreads();

#pragma unroll
    for (int tt = 0; tt < 8; tt++) {
      float kd = kf[tt][d];
      const float4* vr = (const float4*)&vv[tt][v0];
      float4 w0 = vr[0], w1 = vr[1], w2 = vr[2], w3 = vr[3];
      acc[0]  = fmaf(kd, w0.x, acc[0]);
      acc[1]  = fmaf(kd, w0.y, acc[1]);
      acc[2]  = fmaf(kd, w0.z, acc[2]);
      acc[3]  = fmaf(kd, w0.w, acc[3]);
      acc[4]  = fmaf(kd, w1.x, acc[4]);
      acc[5]  = fmaf(kd, w1.y, acc[5]);
      acc[6]  = fmaf(kd, w1.z, acc[6]);
      acc[7]  = fmaf(kd, w1.w, acc[7]);
      acc[8]  = fmaf(kd, w2.x, acc[8]);
      acc[9]  = fmaf(kd, w2.y, acc[9]);
      acc[10] = fmaf(kd, w2.z, acc[10]);
      acc[11] = fmaf(kd, w2.w, acc[11]);
      acc[12] = fmaf(kd, w3.x, acc[12]);
      acc[13] = fmaf(kd, w3.y, acc[13]);
      acc[14] = fmaf(kd, w3.z, acc[14]);
      acc[15] = fmaf(kd, w3.w, acc[15]);
      if (lead) ks += kd;
    }
    __syncthreads();
  }

  float* kvg = g_kv + (bh << 12) + (d << 6) + v0;
#pragma unroll
  for (int i = 0; i < 16; i++) atomicAdd(kvg + i, acc[i]);
  if (lead) atomicAdd(&g_ksum[(bh << 6) + d], ks);
}

// ---------------------------------------------------------------------------
// attn_out: writes bf16 hi/lo directly into g_attn_hi/lo (out-GEMM inputs)
__global__ void __launch_bounds__(128) attn_out_kernel() {
  int bh = blockIdx.x;
  int b = bh >> 4, h = bh & 15;
  int t = (blockIdx.y << 7) + threadIdx.x;

  __shared__ float kvs[4096];
  __shared__ float kss[64];
  __shared__ float ivfs[32];

  const float4* src = (const float4*)(g_kv + (bh << 12));
  for (int i = threadIdx.x; i < 1024; i += 128)
    ((float4*)kvs)[i] = src[i];
  if (threadIdx.x < 64) kss[threadIdx.x] = g_ksum[(bh << 6) + threadIdx.x];
  if (threadIdx.x < 32)
    ivfs[threadIdx.x] = (float)exp(-(double)threadIdx.x * LN1E4_OVER_32);
  __syncthreads();

  size_t base = ((size_t)(b * Tn + t)) * 3072 + (h << 6);

  float qf[64];
#pragma unroll
  for (int pc = 0; pc < 8; pc++) {
    float4 xe4 = *(const float4*)(g_qkv + base + (pc << 2));
    float4 xo4 = *(const float4*)(g_qkv + base + 32 + (pc << 2));
    float xes[4] = {xe4.x, xe4.y, xe4.z, xe4.w};
    float xos[4] = {xo4.x, xo4.y, xo4.z, xo4.w};
#pragma unroll
    for (int j = 0; j < 4; j++) {
      int pp = (pc << 2) + j;
      float2 sc = rope_sc(t, ivfs[pp]);
      float s = sc.x, c = sc.y;
      float qe = fmaf(xes[j], c, -xos[j] * s) * 0.125f;
      float qo = fmaf(xes[j], s, xos[j] * c) * 0.125f;
      qf[pp]      = qe > 0.0f ? qe + 1.0f : expf(qe);
      qf[pp + 32] = qo > 0.0f ? qo + 1.0f : expf(qo);
    }
  }

  float den = 0.0f;
#pragma unroll
  for (int dd = 0; dd < 64; dd++) den = fmaf(qf[dd], kss[dd], den);
  den = fmaxf(den, 1e-6f);
  float inv = 1.0f / den;

  float4 o[16];
#pragma unroll
  for (int i = 0; i < 16; i++) o[i] = make_float4(0.f, 0.f, 0.f, 0.f);
#pragma unroll
  for (int dd = 0; dd < 64; dd++) {
    float qd = qf[dd];
    const float4* row = (const float4*)&kvs[dd << 6];
#pragma unroll
    for (int i = 0; i < 16; i++) {
      float4 rv = row[i];
      o[i].x = fmaf(qd, rv.x, o[i].x);
      o[i].y = fmaf(qd, rv.y, o[i].y);
      o[i].z = fmaf(qd, rv.z, o[i].z);
      o[i].w = fmaf(qd, rv.w, o[i].w);
    }
  }

  size_t obase = (((size_t)(b * Tn + t)) << 10) + (h << 6);
#pragma unroll
  for (int i = 0; i < 16; i++) {
    ushort4 hv, lv;
    split2(o[i].x * inv, hv.x, lv.x);
    split2(o[i].y * inv, hv.y, lv.y);
    split2(o[i].z * inv, hv.z, lv.z);
    split2(o[i].w * inv, hv.w, lv.w);
    *(ushort4*)(g_attn_hi + obase + (i << 2)) = hv;
    *(ushort4*)(g_attn_lo + obase + (i << 2)) = lv;
  }
}

// ---------------------------------------------------------------------------
extern "C" void kernel_launch(void* const* d_in, const int* in_sizes, int n_in,
                              void* d_out, int out_size) {
  (void)in_sizes; (void)n_in; (void)out_size;
  const float* x     = (const float*)d_in[0];
  const float* w_qkv = (const float*)d_in[1];
  const float* w_out = (const float*)d_in[2];
  float* out = (float*)d_out;

  const int GSMEM = 2 * 65536;
  cudaFuncSetAttribute(gemm_mma<3072>, cudaFuncAttributeMaxDynamicSharedMemorySize, GSMEM);
  cudaFuncSetAttribute(gemm_mma<1024>, cudaFuncAttributeMaxDynamicSharedMemorySize, GSMEM);

  conv_x<<<16384, 256>>>(x);
  conv_wqkv<<<3072, 256>>>(w_qkv);
  conv_wout<<<1024, 256>>>(w_out);                          // + zero g_kv/g_ksum
  gemm_mma<3072><<<dim3(24, 128), 256, GSMEM>>>(nullptr);   // qkv -> g_qkv
  kv_accum_kernel<<<dim3(64, 16), 256>>>();
  attn_out_kernel<<<dim3(64, 32), 128>>>();
  gemm_mma<1024><<<dim3(8, 128), 256, GSMEM>>>(out);        // attn @ w_out
}

// round 11
// speedup vs baseline: 2.6555x; 1.0677x over previous
#include <cuda_runtime.h>
#include <cuda_bf16.h>
#include <math.h>
#include <stdint.h>

// Problem: B=4, T=4096, D=1024, H=16, hd=64; M = B*T = 16384
#define Tn 4096

// ---------------------------------------------------------------------------
// Scratch (__device__ globals; no allocations allowed)
__device__ float          g_qkv[50331648];     // [16384,3072] fp32 q|k|v
__device__ __nv_bfloat16  g_x_hi[16777216],   g_x_lo[16777216];    // [16384,1024]
__device__ __nv_bfloat16  g_wqkv_hi[3145728], g_wqkv_lo[3145728];  // [3072,1024]
__device__ __nv_bfloat16  g_wout_hi[1048576], g_wout_lo[1048576];  // [1024,1024]
__device__ __nv_bfloat16  g_attn_hi[16777216],g_attn_lo[16777216]; // [16384,1024]
__device__ float          g_kv[262144];        // [B*H,64,64]
__device__ float          g_ksum[4096];        // [B*H,64]

// ---------------------------------------------------------------------------
// Baseline-PTX helpers (all legal on compute_100)
__device__ __forceinline__ uint32_t smem_u32(const void* p) {
  uint32_t a;
  asm("{ .reg .u64 t; cvta.to.shared.u64 t, %1; cvt.u32.u64 %0, t; }"
      : "=r"(a) : "l"(p));
  return a;
}
__device__ __forceinline__ void cp16(uint32_t dst, const void* src) {
  asm volatile("cp.async.cg.shared.global [%0], [%1], 16;"
               :: "r"(dst), "l"(src) : "memory");
}
__device__ __forceinline__ void cp_commit() {
  asm volatile("cp.async.commit_group;" ::: "memory");
}
template <int n>
__device__ __forceinline__ void cp_wait() {
  asm volatile("cp.async.wait_group %0;" :: "n"(n) : "memory");
}
__device__ __forceinline__ void ldm4(uint32_t& r0, uint32_t& r1, uint32_t& r2,
                                     uint32_t& r3, uint32_t a) {
  asm volatile("ldmatrix.sync.aligned.m8n8.x4.shared.b16 {%0,%1,%2,%3}, [%4];"
               : "=r"(r0), "=r"(r1), "=r"(r2), "=r"(r3) : "r"(a));
}
__device__ __forceinline__ void mma16816(float* c, const uint32_t* a,
                                         const uint32_t* b) {
  asm volatile(
      "mma.sync.aligned.m16n8k16.row.col.f32.bf16.bf16.f32 "
      "{%0,%1,%2,%3}, {%4,%5,%6,%7}, {%8,%9}, {%0,%1,%2,%3};"
      : "+f"(c[0]), "+f"(c[1]), "+f"(c[2]), "+f"(c[3])
      : "r"(a[0]), "r"(a[1]), "r"(a[2]), "r"(a[3]), "r"(b[0]), "r"(b[1]));
}
__device__ __forceinline__ uint32_t swz(uint32_t off) {  // SW128
  return off ^ ((off >> 3) & 0x70);
}

// ---------------------------------------------------------------------------
// fp32 -> bf16 hi/lo split
__device__ __forceinline__ void split2(float v, unsigned short& h,
                                       unsigned short& l) {
  __nv_bfloat16 hb = __float2bfloat16_rn(v);
  h = __bfloat16_as_ushort(hb);
  l = __bfloat16_as_ushort(__float2bfloat16_rn(v - __bfloat162float(hb)));
}

__global__ void __launch_bounds__(256) conv_x(const float* __restrict__ in) {
  int i = blockIdx.x * 256 + threadIdx.x;   // n4 = 4194304
  float4 v = ((const float4*)in)[i];
  ushort4 h, l;
  split2(v.x, h.x, l.x); split2(v.y, h.y, l.y);
  split2(v.z, h.z, l.z); split2(v.w, h.w, l.w);
  ((ushort4*)g_x_hi)[i] = h;
  ((ushort4*)g_x_lo)[i] = l;
}
__global__ void __launch_bounds__(256) conv_wqkv(const float* __restrict__ in) {
  int i = blockIdx.x * 256 + threadIdx.x;   // n4 = 786432
  float4 v = ((const float4*)in)[i];
  ushort4 h, l;
  split2(v.x, h.x, l.x); split2(v.y, h.y, l.y);
  split2(v.z, h.z, l.z); split2(v.w, h.w, l.w);
  ((ushort4*)g_wqkv_hi)[i] = h;
  ((ushort4*)g_wqkv_lo)[i] = l;
}
// Also zeroes g_kv / g_ksum (grid 1024*256 == 262144 == len(g_kv)).
__global__ void __launch_bounds__(256) conv_wout(const float* __restrict__ in) {
  int i = blockIdx.x * 256 + threadIdx.x;   // n4 = 262144
  float4 v = ((const float4*)in)[i];
  ushort4 h, l;
  split2(v.x, h.x, l.x); split2(v.y, h.y, l.y);
  split2(v.z, h.z, l.z); split2(v.w, h.w, l.w);
  ((ushort4*)g_wout_hi)[i] = h;
  ((ushort4*)g_wout_lo)[i] = l;
  g_kv[i] = 0.0f;
  if (i < 4096) g_ksum[i] = 0.0f;
}

// ---------------------------------------------------------------------------
// bf16x3 GEMM via mma.sync: C[m,n] = sum_k A[m,k]*B[n,k].
// CTA 128x128, Kc=64 (SW128 rows), THREE-stage cp.async pipeline (192KB smem),
// 8 warps of 64x32, D += Ah*Bh + Ah*Bl + Al*Bh per k16.
template <int N>
__global__ void __launch_bounds__(256) gemm_mma(float* __restrict__ Cout) {
  extern __shared__ __align__(128) unsigned char smbuf[];
  const __nv_bfloat16* __restrict__ Ah_g = (N == 3072) ? g_x_hi : g_attn_hi;
  const __nv_bfloat16* __restrict__ Al_g = (N == 3072) ? g_x_lo : g_attn_lo;
  const __nv_bfloat16* __restrict__ Bh_g = (N == 3072) ? g_wqkv_hi : g_wout_hi;
  const __nv_bfloat16* __restrict__ Bl_g = (N == 3072) ? g_wqkv_lo : g_wout_lo;
  float* __restrict__ C = (N == 3072) ? g_qkv : Cout;

  int tid = threadIdx.x, lane = tid & 31, wid = tid >> 5;
  int m0 = blockIdx.y << 7, n0 = blockIdx.x << 7;
  int wm = (wid >> 2) << 6;   // warp m-offset: 0 / 64
  int wn = (wid & 3) << 5;    // warp n-offset: 0/32/64/96

  uint32_t sb = smem_u32(smbuf);

  auto stage_load = [&](int buf, int kk) {
    uint32_t d = sb + (uint32_t)buf * 65536u;
#pragma unroll
    for (int it = 0; it < 4; it++) {
      int c = (it << 8) + tid;
      int r = c >> 3, sg = c & 7;                 // row 0..127, 16B-seg 0..7
      uint32_t off = swz((uint32_t)((r << 7) + (sg << 4)));
      size_t ga = (size_t)(m0 + r) * 1024 + kk + (sg << 3);
      size_t gb = (size_t)(n0 + r) * 1024 + kk + (sg << 3);
      cp16(d + off,         Ah_g + ga);
      cp16(d + 16384 + off, Al_g + ga);
      cp16(d + 32768 + off, Bh_g + gb);
      cp16(d + 49152 + off, Bl_g + gb);
    }
  };

  float acc[4][4][4];
#pragma unroll
  for (int i = 0; i < 4; i++)
#pragma unroll
    for (int j = 0; j < 4; j++)
#pragma unroll
      for (int q = 0; q < 4; q++) acc[i][j][q] = 0.0f;

  stage_load(0, 0);  cp_commit();
  stage_load(1, 64); cp_commit();
  int lbuf = 2, cbuf = 0;

  for (int ch = 0; ch < 16; ch++) {
    if (ch + 2 < 16) {
      stage_load(lbuf, (ch + 2) << 6);
      cp_commit();
      if (++lbuf == 3) lbuf = 0;
      cp_wait<2>();
    } else if (ch == 14) {
      cp_wait<1>();
    } else {
      cp_wait<0>();
    }
    __syncthreads();
    uint32_t bs = sb + (uint32_t)cbuf * 65536u;

#pragma unroll
    for (int k16 = 0; k16 < 4; k16++) {
      uint32_t Ah[4][4], Al[4][4], Bh[4][2], Bl[4][2];
      int ar = wm + (lane & 15);
      uint32_t ac = (uint32_t)((k16 << 5) + ((lane >> 4) << 4));
#pragma unroll
      for (int mt = 0; mt < 4; mt++) {
        uint32_t off = swz((uint32_t)(((ar + (mt << 4)) << 7)) + ac);
        ldm4(Ah[mt][0], Ah[mt][1], Ah[mt][2], Ah[mt][3], bs + off);
        ldm4(Al[mt][0], Al[mt][1], Al[mt][2], Al[mt][3], bs + 16384 + off);
      }
      int br = wn + ((lane >> 4) << 3) + (lane & 7);
      uint32_t bc = (uint32_t)((k16 << 5) + (((lane >> 3) & 1) << 4));
#pragma unroll
      for (int np = 0; np < 2; np++) {
        uint32_t off = swz((uint32_t)(((br + (np << 4)) << 7)) + bc);
        uint32_t r0, r1, r2, r3;
        ldm4(r0, r1, r2, r3, bs + 32768 + off);
        Bh[np * 2][0] = r0; Bh[np * 2][1] = r1;
        Bh[np * 2 + 1][0] = r2; Bh[np * 2 + 1][1] = r3;
        ldm4(r0, r1, r2, r3, bs + 49152 + off);
        Bl[np * 2][0] = r0; Bl[np * 2][1] = r1;
        Bl[np * 2 + 1][0] = r2; Bl[np * 2 + 1][1] = r3;
      }
#pragma unroll
      for (int mt = 0; mt < 4; mt++)
#pragma unroll
        for (int nt = 0; nt < 4; nt++) {
          mma16816(acc[mt][nt], Ah[mt], Bh[nt]);
          mma16816(acc[mt][nt], Ah[mt], Bl[nt]);
          mma16816(acc[mt][nt], Al[mt], Bh[nt]);
        }
    }
    __syncthreads();
    if (++cbuf == 3) cbuf = 0;
  }

  int g = lane >> 2, tg = lane & 3;
#pragma unroll
  for (int mt = 0; mt < 4; mt++) {
    int row = m0 + wm + (mt << 4) + g;
#pragma unroll
    for (int nt = 0; nt < 4; nt++) {
      int col = n0 + wn + (nt << 3) + (tg << 1);
      float* p0 = C + (size_t)row * N + col;
      float* p1 = C + (size_t)(row + 8) * N + col;
      p0[0] = acc[mt][nt][0]; p0[1] = acc[mt][nt][1];
      p1[0] = acc[mt][nt][2]; p1[1] = acc[mt][nt][3];
    }
  }
}

// ---------------------------------------------------------------------------
// RoPE angle, matching reference fp32 rounding.
#define LN1E4_OVER_32 0.28782308398950104
#define TWO_PI_D 6.283185307179586
#define INV2PI_D 0.15915494309189535

__device__ __forceinline__ float2 rope_sc(int t, float ivf_f) {
  float th_f = __fmul_rn((float)t, ivf_f);
  double th = (double)th_f;
  float rf = (float)(th - floor(th * INV2PI_D) * TWO_PI_D);
  return make_float2(sinf(rf), cosf(rf));
}

// ---------------------------------------------------------------------------
// kv accumulate; 128 tokens per block (grid 64x32) for more parallelism.
__global__ void __launch_bounds__(256) kv_accum_kernel() {
  int bh = blockIdx.x;
  int b = bh >> 4, h = bh & 15;
  int t0 = blockIdx.y << 7;
  int tid = threadIdx.x;
  int d = tid >> 2;
  int v0 = (tid & 3) << 4;
  bool lead = (tid & 3) == 0;
  int p = tid & 31;
  int ltt = tid >> 5;

  __shared__ float kf[8][64];
  __shared__ float vv[8][64];

  float acc[16];
#pragma unroll
  for (int i = 0; i < 16; i++) acc[i] = 0.0f;
  float ks = 0.0f;

  float ivf_f = (float)exp(-(double)p * LN1E4_OVER_32);

  for (int ts = 0; ts < 128; ts += 8) {
    int t = t0 + ts + ltt;
    float2 sc = rope_sc(t, ivf_f);
    float s = sc.x, c = sc.y;

    size_t base = ((size_t)(b * Tn + t)) * 3072 + (h << 6);
    float xe = g_qkv[base + 1024 + p];
    float xo = g_qkv[base + 1056 + p];
    float ke = fmaf(xe, c, -xo * s);
    float ko = fmaf(xe, s, xo * c);
    kf[ltt][p]      = ke > 0.0f ? ke + 1.0f : expf(ke);
    kf[ltt][p + 32] = ko > 0.0f ? ko + 1.0f : expf(ko);
    vv[ltt][p]      = g_qkv[base + 2048 + p];
    vv[ltt][p + 32] = g_qkv[base + 2080 + p];
    __syncthreads();

#pragma unroll
    for (int tt = 0; tt < 8; tt++) {
      float kd = kf[tt][d];
      const float4* vr = (const float4*)&vv[tt][v0];
      float4 w0 = vr[0], w1 = vr[1], w2 = vr[2], w3 = vr[3];
      acc[0]  = fmaf(kd, w0.x, acc[0]);
      acc[1]  = fmaf(kd, w0.y, acc[1]);
      acc[2]  = fmaf(kd, w0.z, acc[2]);
      acc[3]  = fmaf(kd, w0.w, acc[3]);
      acc[4]  = fmaf(kd, w1.x, acc[4]);
      acc[5]  = fmaf(kd, w1.y, acc[5]);
      acc[6]  = fmaf(kd, w1.z, acc[6]);
      acc[7]  = fmaf(kd, w1.w, acc[7]);
      acc[8]  = fmaf(kd, w2.x, acc[8]);
      acc[9]  = fmaf(kd, w2.y, acc[9]);
      acc[10] = fmaf(kd, w2.z, acc[10]);
      acc[11] = fmaf(kd, w2.w, acc[11]);
      acc[12] = fmaf(kd, w3.x, acc[12]);
      acc[13] = fmaf(kd, w3.y, acc[13]);
      acc[14] = fmaf(kd, w3.z, acc[14]);
      acc[15] = fmaf(kd, w3.w, acc[15]);
      if (lead) ks += kd;
    }
    __syncthreads();
  }

  float* kvg = g_kv + (bh << 12) + (d << 6) + v0;
#pragma unroll
  for (int i = 0; i < 16; i++) atomicAdd(kvg + i, acc[i]);
  if (lead) atomicAdd(&g_ksum[(bh << 6) + d], ks);
}

// ---------------------------------------------------------------------------
// attn_out: 256 threads = 128 tokens x 2 column-halves; qf staged in DYNAMIC
// smem (50KB > 48KB static cap). Layout: kvs[4096] | qfs[128*65] | kss[64] |
// ivfs[32]. Low regs -> high occupancy. Writes bf16 hi/lo.
#define AO_SMEM ((4096 + 128 * 65 + 64 + 32) * 4)
__global__ void __launch_bounds__(256) attn_out_kernel() {
  extern __shared__ __align__(16) float dynsm[];
  float* kvs  = dynsm;                 // [4096]
  float* qfs  = dynsm + 4096;          // [128][65] padded
  float* kss  = qfs + 128 * 65;        // [64]
  float* ivfs = kss + 64;              // [32]

  int bh = blockIdx.x;
  int b = bh >> 4, h = bh & 15;
  int tid = threadIdx.x;
  int tt = tid & 127;          // token within block
  int ph = tid >> 7;           // half 0/1
  int t = (blockIdx.y << 7) + tt;

  const float4* src = (const float4*)(g_kv + (bh << 12));
  for (int i = tid; i < 1024; i += 256)
    ((float4*)kvs)[i] = src[i];
  if (tid < 64) kss[tid] = g_ksum[(bh << 6) + tid];
  if (tid < 32) ivfs[tid] = (float)exp(-(double)tid * LN1E4_OVER_32);
  __syncthreads();

  size_t base = ((size_t)(b * Tn + t)) * 3072 + (h << 6);
  float* qrow = qfs + tt * 65;

  // Phase B: this thread computes RoPE pairs [p0, p0+16) -> 32 qf values
  int p0 = ph << 4;
#pragma unroll
  for (int pc = 0; pc < 4; pc++) {
    float4 xe4 = *(const float4*)(g_qkv + base + p0 + (pc << 2));
    float4 xo4 = *(const float4*)(g_qkv + base + 32 + p0 + (pc << 2));
    float xes[4] = {xe4.x, xe4.y, xe4.z, xe4.w};
    float xos[4] = {xo4.x, xo4.y, xo4.z, xo4.w};
#pragma unroll
    for (int j = 0; j < 4; j++) {
      int pp = p0 + (pc << 2) + j;
      float2 sc = rope_sc(t, ivfs[pp]);
      float s = sc.x, c = sc.y;
      float qe = fmaf(xes[j], c, -xos[j] * s) * 0.125f;
      float qo = fmaf(xes[j], s, xos[j] * c) * 0.125f;
      qrow[pp]      = qe > 0.0f ? qe + 1.0f : expf(qe);
      qrow[pp + 32] = qo > 0.0f ? qo + 1.0f : expf(qo);
    }
  }
  __syncthreads();

  float den = 0.0f;
#pragma unroll
  for (int dd = 0; dd < 64; dd++) den = fmaf(qrow[dd], kss[dd], den);
  den = fmaxf(den, 1e-6f);
  float inv = 1.0f / den;

  // Phase C: accumulate this half's 32 output columns
  int c0 = ph << 5;
  float4 o[8];
#pragma unroll
  for (int i = 0; i < 8; i++) o[i] = make_float4(0.f, 0.f, 0.f, 0.f);
#pragma unroll
  for (int dd = 0; dd < 64; dd++) {
    float qd = qrow[dd];
    const float4* row = (const float4*)&kvs[(dd << 6) + c0];
#pragma unroll
    for (int i = 0; i < 8; i++) {
      float4 rv = row[i];
      o[i].x = fmaf(qd, rv.x, o[i].x);
      o[i].y = fmaf(qd, rv.y, o[i].y);
      o[i].z = fmaf(qd, rv.z, o[i].z);
      o[i].w = fmaf(qd, rv.w, o[i].w);
    }
  }

  size_t obase = (((size_t)(b * Tn + t)) << 10) + (h << 6) + c0;
#pragma unroll
  for (int i = 0; i < 8; i++) {
    ushort4 hv, lv;
    split2(o[i].x * inv, hv.x, lv.x);
    split2(o[i].y * inv, hv.y, lv.y);
    split2(o[i].z * inv, hv.z, lv.z);
    split2(o[i].w * inv, hv.w, lv.w);
    *(ushort4*)(g_attn_hi + obase + (i << 2)) = hv;
    *(ushort4*)(g_attn_lo + obase + (i << 2)) = lv;
  }
}

// ---------------------------------------------------------------------------
extern "C" void kernel_launch(void* const* d_in, const int* in_sizes, int n_in,
                              void* d_out, int out_size) {
  (void)in_sizes; (void)n_in; (void)out_size;
  const float* x     = (const float*)d_in[0];
  const float* w_qkv = (const float*)d_in[1];
  const float* w_out = (const float*)d_in[2];
  float* out = (float*)d_out;

  const int GSMEM = 3 * 65536;   // 192KB, 3-stage pipeline
  cudaFuncSetAttribute(gemm_mma<3072>, cudaFuncAttributeMaxDynamicSharedMemorySize, GSMEM);
  cudaFuncSetAttribute(gemm_mma<1024>, cudaFuncAttributeMaxDynamicSharedMemorySize, GSMEM);
  cudaFuncSetAttribute(attn_out_kernel, cudaFuncAttributeMaxDynamicSharedMemorySize, AO_SMEM);

  conv_x<<<16384, 256>>>(x);
  conv_wqkv<<<3072, 256>>>(w_qkv);
  conv_wout<<<1024, 256>>>(w_out);                          // + zero g_kv/g_ksum
  gemm_mma<3072><<<dim3(24, 128), 256, GSMEM>>>(nullptr);   // qkv -> g_qkv
  kv_accum_kernel<<<dim3(64, 32), 256>>>();
  attn_out_kernel<<<dim3(64, 32), 256, AO_SMEM>>>();
  gemm_mma<1024><<<dim3(8, 128), 256, GSMEM>>>(out);        // attn @ w_out
}